// round 7
// baseline (speedup 1.0000x reference)
#include <cuda_runtime.h>
#include <math.h>

// N=100000, E=1280000, IN_D=256, FEAT=HID=OUT=64
#define NMAX 100000
#define EMAX 1280000
#define NEG_SLOPE 0.2f

// ---------------- scratch ----------------
__device__ float g_hA[NMAX * 64];
__device__ float g_hB[NMAX * 64];
__device__ float g_lin[NMAX * 64];
__device__ float g_es[NMAX];
__device__ float g_ed[NMAX];
__device__ int   g_deg[NMAX];
__device__ int   g_cur[NMAX];
__device__ int   g_rowptr[NMAX + 1];
__device__ int   g_col[EMAX];

__device__ __forceinline__ float leaky(float x) { return x > 0.f ? x : NEG_SLOPE * x; }

// f32x2 packed math (Blackwell): one FMA-pipe instruction = 2 fp32 FMAs
__device__ __forceinline__ void fma2(unsigned long long& d, unsigned long long a, unsigned long long b) {
    asm("fma.rn.f32x2 %0, %1, %2, %0;" : "+l"(d) : "l"(a), "l"(b));
}
__device__ __forceinline__ unsigned long long pack2(float lo, float hi) {
    unsigned long long r;
    asm("mov.b64 %0, {%1, %2};" : "=l"(r) : "f"(lo), "f"(hi));
    return r;
}
__device__ __forceinline__ float2 unpack2(unsigned long long v) {
    float2 f;
    asm("mov.b64 {%0, %1}, %2;" : "=f"(f.x), "=f"(f.y) : "l"(v));
    return f;
}

// ---------------- CSR build ----------------
__global__ void k_hist(const int* __restrict__ dst, int e) {
    int i = blockIdx.x * blockDim.x + threadIdx.x;
    if (i < e) atomicAdd(&g_deg[dst[i]], 1);
}
__global__ void k_scan(int n) {
    __shared__ int s[1024];
    int t = threadIdx.x;
    int chunk = (n + 1023) >> 10;
    int beg = t * chunk;
    int end = beg + chunk; if (end > n) end = n;
    int sum = 0;
    for (int i = beg; i < end; i++) sum += g_deg[i];
    s[t] = sum;
    __syncthreads();
    for (int off = 1; off < 1024; off <<= 1) {
        int v = 0;
        if (t >= off) v = s[t - off];
        __syncthreads();
        if (t >= off) s[t] += v;
        __syncthreads();
    }
    int prefix = (t == 0) ? 0 : s[t - 1];
    for (int i = beg; i < end; i++) {
        g_rowptr[i] = prefix;
        prefix += g_deg[i];
        g_cur[i] = 0;
    }
    if (t == 1023) g_rowptr[n] = s[1023];
}
__global__ void k_scatter(const int* __restrict__ src, const int* __restrict__ dst, int e) {
    int i = blockIdx.x * blockDim.x + threadIdx.x;
    if (i >= e) return;
    int d = dst[i];
    int pos = g_rowptr[d] + atomicAdd(&g_cur[d], 1);
    g_col[pos] = src[i];
}

// ---------------- GEMM: C[n x 64] = A[n x K] @ B[K x 64] ----------------
// 128x64 tile per block, 256 threads, 8 rows x 4 cols per thread, f32x2 FMAs.
// minBlocksPerMultiprocessor=3 to lift occupancy (was 2 blocks/SM at 102 regs).
#define ASTR 68
#define BSTR 68
__global__ void __launch_bounds__(256, 3) k_gemm128(
        const float* __restrict__ A, const float* __restrict__ B,
        const float* __restrict__ bias,
        const float* __restrict__ a_s, const float* __restrict__ a_d,
        float* __restrict__ C, int n, int K) {
    __shared__ float As[128 * ASTR];   // As[m][k]
    __shared__ float Bs[64 * BSTR];    // Bs[k][j]
    const int tid = threadIdx.x;
    const int tx = tid & 15;
    const int ty = tid >> 4;
    const int row0 = blockIdx.x * 128;

    unsigned long long acc[8][2];
#pragma unroll
    for (int i = 0; i < 8; i++) { acc[i][0] = 0ull; acc[i][1] = 0ull; }

    for (int k0 = 0; k0 < K; k0 += 64) {
#pragma unroll
        for (int l = 0; l < 8; l++) {
            int idx = tid + l * 256;
            int m = idx >> 4;
            int kq = idx & 15;
            int grow = row0 + m;
            float4 v = make_float4(0.f, 0.f, 0.f, 0.f);
            if (grow < n)
                v = *reinterpret_cast<const float4*>(A + (size_t)grow * K + k0 + kq * 4);
            *reinterpret_cast<float4*>(&As[m * ASTR + kq * 4]) = v;
        }
#pragma unroll
        for (int l = 0; l < 4; l++) {
            int idx = tid + l * 256;
            int k = idx >> 4;
            int jq = idx & 15;
            float4 v = *reinterpret_cast<const float4*>(B + (size_t)(k0 + k) * 64 + jq * 4);
            *reinterpret_cast<float4*>(&Bs[k * BSTR + jq * 4]) = v;
        }
        __syncthreads();
#pragma unroll 4
        for (int k = 0; k < 64; k++) {
            float4 b = *reinterpret_cast<const float4*>(&Bs[k * BSTR + tx * 4]);
            unsigned long long b01 = pack2(b.x, b.y);
            unsigned long long b23 = pack2(b.z, b.w);
#pragma unroll
            for (int i = 0; i < 8; i++) {
                float a = As[(ty * 8 + i) * ASTR + k];
                unsigned long long aa = pack2(a, a);
                fma2(acc[i][0], aa, b01);
                fma2(acc[i][1], aa, b23);
            }
        }
        __syncthreads();
    }

    float4 asv = make_float4(0.f, 0.f, 0.f, 0.f), adv = asv, bv = asv;
    if (a_s) {
        asv = *reinterpret_cast<const float4*>(a_s + tx * 4);
        adv = *reinterpret_cast<const float4*>(a_d + tx * 4);
    }
    if (bias) bv = *reinterpret_cast<const float4*>(bias + tx * 4);

#pragma unroll
    for (int i = 0; i < 8; i++) {
        int grow = row0 + ty * 8 + i;
        float2 p0 = unpack2(acc[i][0]);
        float2 p1 = unpack2(acc[i][1]);
        float c0 = p0.x, c1 = p0.y, c2 = p1.x, c3 = p1.y;
        if (bias) { c0 += bv.x; c1 += bv.y; c2 += bv.z; c3 += bv.w; }
        if (grow < n)
            *reinterpret_cast<float4*>(C + (size_t)grow * 64 + tx * 4) = make_float4(c0, c1, c2, c3);
        if (a_s) {
            float es = c0 * asv.x + c1 * asv.y + c2 * asv.z + c3 * asv.w;
            float ed = c0 * adv.x + c1 * adv.y + c2 * adv.z + c3 * adv.w;
#pragma unroll
            for (int o = 8; o; o >>= 1) {
                es += __shfl_xor_sync(0xffffffffu, es, o);
                ed += __shfl_xor_sync(0xffffffffu, ed, o);
            }
            if (tx == 0 && grow < n) { g_es[grow] = es; g_ed[grow] = ed; }
        }
    }
}

// ---------------- aggregation: warp per dst, uniform edge loop ----------------
// All lanes redundantly load (s, es[s]) at uniform addresses (one L2 request) and
// compute ex — no shuffles, no reductions (den is lane-uniform). Lane owns feature
// pair (2*lane, 2*lane+1): one LDG.64 + one fma.f32x2 per edge. 4x unroll for MLP.
// mode 0: relu(out + bias); mode 1: (out + bias) then row L2-normalize
__global__ void __launch_bounds__(256) k_agg(const float* __restrict__ bias,
                                             float* __restrict__ out, int n, int mode) {
    int w = (blockIdx.x * blockDim.x + threadIdx.x) >> 5;
    if (w >= n) return;
    int lane = threadIdx.x & 31;
    int beg = g_rowptr[w], end = g_rowptr[w + 1];
    float edd = g_ed[w];

    float ex_self = __expf(leaky(g_es[w] + edd));
    float2 hv = *reinterpret_cast<const float2*>(g_lin + (size_t)w * 64 + 2 * lane);
    unsigned long long acc = 0ull;
    fma2(acc, pack2(ex_self, ex_self), pack2(hv.x, hv.y));
    float den = ex_self;

    int k = beg;
    for (; k + 4 <= end; k += 4) {
        int s0 = g_col[k];
        int s1 = g_col[k + 1];
        int s2 = g_col[k + 2];
        int s3 = g_col[k + 3];
        float q0 = g_es[s0], q1 = g_es[s1], q2 = g_es[s2], q3 = g_es[s3];
        float2 v0 = *reinterpret_cast<const float2*>(g_lin + (size_t)s0 * 64 + 2 * lane);
        float2 v1 = *reinterpret_cast<const float2*>(g_lin + (size_t)s1 * 64 + 2 * lane);
        float2 v2 = *reinterpret_cast<const float2*>(g_lin + (size_t)s2 * 64 + 2 * lane);
        float2 v3 = *reinterpret_cast<const float2*>(g_lin + (size_t)s3 * 64 + 2 * lane);
        float e0 = __expf(leaky(q0 + edd));
        float e1 = __expf(leaky(q1 + edd));
        float e2 = __expf(leaky(q2 + edd));
        float e3 = __expf(leaky(q3 + edd));
        den += e0 + e1 + e2 + e3;
        fma2(acc, pack2(e0, e0), pack2(v0.x, v0.y));
        fma2(acc, pack2(e1, e1), pack2(v1.x, v1.y));
        fma2(acc, pack2(e2, e2), pack2(v2.x, v2.y));
        fma2(acc, pack2(e3, e3), pack2(v3.x, v3.y));
    }
    for (; k < end; k++) {
        int s = g_col[k];
        float ex = __expf(leaky(g_es[s] + edd));
        float2 v = *reinterpret_cast<const float2*>(g_lin + (size_t)s * 64 + 2 * lane);
        den += ex;
        fma2(acc, pack2(ex, ex), pack2(v.x, v.y));
    }

    float inv = 1.f / (den + 1e-16f);
    float2 bvec = *reinterpret_cast<const float2*>(bias + 2 * lane);
    float2 av = unpack2(acc);
    float o0 = av.x * inv + bvec.x;
    float o1 = av.y * inv + bvec.y;
    if (mode == 0) {
        o0 = fmaxf(o0, 0.f);
        o1 = fmaxf(o1, 0.f);
    } else {
        float ss = o0 * o0 + o1 * o1;
#pragma unroll
        for (int o = 16; o; o >>= 1) ss += __shfl_xor_sync(0xffffffffu, ss, o);
        float nrm = fmaxf(sqrtf(ss), 1e-12f);
        o0 /= nrm; o1 /= nrm;
    }
    *reinterpret_cast<float2*>(out + (size_t)w * 64 + 2 * lane) = make_float2(o0, o1);
}

// ---------------- launch ----------------
extern "C" void kernel_launch(void* const* d_in, const int* in_sizes, int n_in,
                              void* d_out, int out_size) {
    const float* x     = (const float*)d_in[0];
    const int*   src   = (const int*)d_in[1];
    const int*   dst   = (const int*)d_in[2];
    const float* lin_w = (const float*)d_in[3];
    const float* lin_b = (const float*)d_in[4];
    const float* W[3]  = { (const float*)d_in[5],  (const float*)d_in[9],  (const float*)d_in[13] };
    const float* AS[3] = { (const float*)d_in[6],  (const float*)d_in[10], (const float*)d_in[14] };
    const float* AD[3] = { (const float*)d_in[7],  (const float*)d_in[11], (const float*)d_in[15] };
    const float* BI[3] = { (const float*)d_in[8],  (const float*)d_in[12], (const float*)d_in[16] };

    const int n = in_sizes[0] / 256;   // 100000
    const int e = in_sizes[1];         // 1280000

    float *hA, *hB, *lin;
    int *degp;
    cudaGetSymbolAddress((void**)&hA,   g_hA);
    cudaGetSymbolAddress((void**)&hB,   g_hB);
    cudaGetSymbolAddress((void**)&lin,  g_lin);
    cudaGetSymbolAddress((void**)&degp, g_deg);

    const int TB = 256;
    dim3 gE((e + TB - 1) / TB);
    dim3 gG((n + 127) / 128);
    dim3 gW((n + 7) / 8);

    // CSR by dst (graph fixed across all 3 layers)
    cudaMemsetAsync(degp, 0, (size_t)n * sizeof(int));
    k_hist<<<gE, TB>>>(dst, e);
    k_scan<<<1, 1024>>>(n);
    k_scatter<<<gE, TB>>>(src, dst, e);

    // feature_pre: h0 = x @ lin_w + lin_b
    k_gemm128<<<gG, TB>>>(x, lin_w, lin_b, nullptr, nullptr, hA, n, 256);

    // Layer 1
    k_gemm128<<<gG, TB>>>(hA, W[0], nullptr, AS[0], AD[0], lin, n, 64);
    k_agg<<<gW, TB>>>(BI[0], hB, n, 0);

    // Layer 2
    k_gemm128<<<gG, TB>>>(hB, W[1], nullptr, AS[1], AD[1], lin, n, 64);
    k_agg<<<gW, TB>>>(BI[1], hA, n, 0);

    // Layer 3 (+ row L2 normalize) -> d_out
    k_gemm128<<<gG, TB>>>(hA, W[2], nullptr, AS[2], AD[2], lin, n, 64);
    k_agg<<<gW, TB>>>(BI[2], (float*)d_out, n, 1);
}